// round 8
// baseline (speedup 1.0000x reference)
#include <cuda_runtime.h>
#include <cuda_bf16.h>
#include <cstdint>
#include <math_constants.h>

// VectorQuantizer via mma.sync bf16 (3-pass emulated fp32 GEMM) + exact rescore.
// x [32,64,64,64] f32, emb [512,64] f32 -> out [32,64,64,64] f32.
// tcgen05 unavailable (harness targets sm_103 plain); mma.sync m16n8k16 bf16 is
// baseline sm_80+ and runs on the tensor pipe.
// R8 fix: all shuffles in the divergent finalize region are quad-scoped
// (mask = 0xF << (qr*4)) — full-mask shuffles under quad-divergent branches
// deadlocked R7.

#define VQ_K 512
#define VQ_D 64
#define VQ_HW 4096
#define NPIX 131072
#define TILE_M 128
#define NTILES 1024
#define THREADS 256
#define CAP 6
#define MARGIN 1e-4f
#define XFS 132

// ---- shared memory layout (bytes) ----
#define SM_B0  0         // codebook hi bf16 [512 rows][128B]   64 KB
#define SM_B1  65536     // codebook lo bf16                    64 KB
#define SM_A0  131072    // x tile hi bf16 [128 rows][128B]     16 KB
#define SM_A1  147456    // x tile lo bf16                      16 KB
#define SM_XF  163840    // x tile f32 [64][XFS]                33792 B
#define SM_ESQ 197632    // f32 e_sq[512]
#define SM_XSQ 199680    // f32 xsq[128]
#define SM_WIN 200192    // int winners[128]
#define SMEM_TOTAL 200704

// Pair-permuted row layout (per 64-elem row, 128B):
//  row split into 4 ksteps of 16 elems; each kstep = 4 units of 8B;
//  unit 'slot' holds [pair(2*slot), pair(2*slot+8)] (4B halves), so an LDS.64
//  at (kstep, g=lane%4) yields mma B/A regs {(c0,c1),(c0+8,c0+9)} directly.
//  Units XOR-swizzled by (row & 7) for conflict-free quad access.
__device__ __forceinline__ int frag_off(int row, int ks, int g) {
    return row * 128 + ((((ks << 2) | g)) ^ (row & 7)) * 8;
}
__device__ __forceinline__ void stage_bf16(char* b0, char* b1, int row, int c, float v) {
    const int ks = c >> 4, w = c & 15, pid = w >> 1, slot = pid & 3, half = pid >> 2;
    const int unit = ((ks << 2) | slot) ^ (row & 7);
    const int off = row * 128 + unit * 8 + half * 4 + (c & 1) * 2;
    const __nv_bfloat16 hi = __float2bfloat16(v);
    *(__nv_bfloat16*)(b0 + off) = hi;
    *(__nv_bfloat16*)(b1 + off) = __float2bfloat16(v - __bfloat162float(hi));
}

__device__ __forceinline__ void hmma(float& d0, float& d1, float& d2, float& d3,
                                     uint32_t a0, uint32_t a1, uint32_t a2, uint32_t a3,
                                     uint32_t b0, uint32_t b1) {
    asm volatile(
        "mma.sync.aligned.m16n8k16.row.col.f32.bf16.bf16.f32 "
        "{%0,%1,%2,%3}, {%4,%5,%6,%7}, {%8,%9}, {%0,%1,%2,%3};"
        : "+f"(d0), "+f"(d1), "+f"(d2), "+f"(d3)
        : "r"(a0), "r"(a1), "r"(a2), "r"(a3), "r"(b0), "r"(b1));
}

// Exact fp32 distance, numerics identical to round-1 (bit-matched reference).
__device__ __forceinline__ float exact_dist(const float* __restrict__ xf,
                                            const float* __restrict__ emb,
                                            float xsq, float esqk, int k, int p) {
    const float4* er = reinterpret_cast<const float4*>(emb + (size_t)k * VQ_D);
    float dot = 0.0f;
    #pragma unroll
    for (int q = 0; q < 16; q++) {
        const float4 f = __ldg(er + q);
        dot = __fmaf_rn(xf[(4 * q + 0) * XFS + p], f.x, dot);
        dot = __fmaf_rn(xf[(4 * q + 1) * XFS + p], f.y, dot);
        dot = __fmaf_rn(xf[(4 * q + 2) * XFS + p], f.z, dot);
        dot = __fmaf_rn(xf[(4 * q + 3) * XFS + p], f.w, dot);
    }
    return __fadd_rn(__fadd_rn(xsq, esqk), __fmul_rn(-2.0f, dot));
}

__global__ __launch_bounds__(THREADS, 1)
void vq_hmma_kernel(const float* __restrict__ x,
                    const float* __restrict__ emb,
                    float* __restrict__ out) {
    extern __shared__ char sm[];
    char* smB0 = sm + SM_B0;
    char* smB1 = sm + SM_B1;
    char* smA0 = sm + SM_A0;
    char* smA1 = sm + SM_A1;
    float* xf      = reinterpret_cast<float*>(sm + SM_XF);
    float* esq     = reinterpret_cast<float*>(sm + SM_ESQ);
    float* xsqs    = reinterpret_cast<float*>(sm + SM_XSQ);
    int*   winners = reinterpret_cast<int*>(sm + SM_WIN);

    const int tid  = threadIdx.x;
    const int wid  = tid >> 5;
    const int lane = tid & 31;
    const int g    = lane & 3;        // quad lane
    const int qr   = lane >> 2;       // group id
    const unsigned qmask = 0xFu << (qr * 4);   // this thread's quad

    // ---- prologue: stage codebook (bf16 hi/lo) + exact e_sq ----
    #pragma unroll 4
    for (int it = 0; it < 32; it++) {
        const int lin = it * THREADS + tid;          // 8192 float4s
        const int k = lin >> 4, q = lin & 15;
        const float4 f = __ldg(reinterpret_cast<const float4*>(emb + k * VQ_D) + q);
        const int c = q * 4;
        stage_bf16(smB0, smB1, k, c + 0, f.x);
        stage_bf16(smB0, smB1, k, c + 1, f.y);
        stage_bf16(smB0, smB1, k, c + 2, f.z);
        stage_bf16(smB0, smB1, k, c + 3, f.w);
    }
    for (int k = tid; k < VQ_K; k += THREADS) {
        const float4* er = reinterpret_cast<const float4*>(emb + k * VQ_D);
        float s = 0.0f;
        #pragma unroll
        for (int q = 0; q < 16; q++) {
            const float4 f = __ldg(er + q);
            s = __fadd_rn(s, __fmul_rn(f.x, f.x));
            s = __fadd_rn(s, __fmul_rn(f.y, f.y));
            s = __fadd_rn(s, __fmul_rn(f.z, f.z));
            s = __fadd_rn(s, __fmul_rn(f.w, f.w));
        }
        esq[k] = s;
    }
    __syncthreads();

    for (int tile = blockIdx.x; tile < NTILES; tile += gridDim.x) {
        const int pix0 = tile * TILE_M;
        const int bIdx = pix0 >> 12;
        const int hw0  = pix0 & 4095;
        const float* xbase = x + (size_t)bIdx * VQ_D * VQ_HW + hw0;
        float* obase = out + (size_t)bIdx * VQ_D * VQ_HW + hw0;

        // ---- stage x tile: f32 copy + bf16 hi/lo fragment tiles ----
        #pragma unroll
        for (int it = 0; it < 8; it++) {
            const int lin = it * THREADS + tid;      // 2048 float4s
            const int c = lin >> 5, q = lin & 31, p = q * 4;
            const float4 f = __ldg(reinterpret_cast<const float4*>(xbase + (size_t)c * VQ_HW + p));
            *reinterpret_cast<float4*>(xf + c * XFS + p) = f;
            stage_bf16(smA0, smA1, p + 0, c, f.x);
            stage_bf16(smA0, smA1, p + 1, c, f.y);
            stage_bf16(smA0, smA1, p + 2, c, f.z);
            stage_bf16(smA0, smA1, p + 3, c, f.w);
        }
        __syncthreads();

        // xsq per pixel row (sequential order, matches reference)
        if (tid < TILE_M) {
            float s = 0.0f;
            #pragma unroll
            for (int c = 0; c < VQ_D; c++) {
                const float v = xf[c * XFS + tid];
                s = __fadd_rn(s, __fmul_rn(v, v));
            }
            xsqs[tid] = s;
        }

        // ---- per-warp m16 x n512 x k64 GEMM ----
        const int r0t = wid * 16 + qr;       // tile row of this thread's r0
        const int r1t = r0t + 8;

        uint2 a0r0[4], a0r1[4], a1r0[4], a1r1[4];
        #pragma unroll
        for (int ks = 0; ks < 4; ks++) {
            a0r0[ks] = *reinterpret_cast<const uint2*>(smA0 + frag_off(r0t, ks, g));
            a0r1[ks] = *reinterpret_cast<const uint2*>(smA0 + frag_off(r1t, ks, g));
            a1r0[ks] = *reinterpret_cast<const uint2*>(smA1 + frag_off(r0t, ks, g));
            a1r1[ks] = *reinterpret_cast<const uint2*>(smA1 + frag_off(r1t, ks, g));
        }

        // candidate state per row (r0, r1)
        float cm[2]  = {CUDART_INF_F, CUDART_INF_F};
        float cthr[2] = {CUDART_INF_F, CUDART_INF_F};
        int   cn[2] = {0, 0};
        int   cov[2] = {0, 0};
        int   cidx[2][CAP];
        float cval[2][CAP];

        #define CUPD(rr, s, kk)                                                     \
            if ((s) <= cthr[rr]) {                                                  \
                if ((s) < cm[rr]) { cm[rr] = (s); cthr[rr] = (s) + MARGIN; }        \
                if (cn[rr] < CAP) { cidx[rr][cn[rr]] = (kk); cval[rr][cn[rr]] = (s);\
                                    cn[rr]++; }                                     \
                else cov[rr] = 1;                                                   \
            }

        for (int nc = 0; nc < 8; nc++) {          // 8 chunks of 64 codes
            float acc[8][4];
            #pragma unroll
            for (int nf = 0; nf < 8; nf++) {
                acc[nf][0] = 0.f; acc[nf][1] = 0.f; acc[nf][2] = 0.f; acc[nf][3] = 0.f;
            }
            #pragma unroll
            for (int ks = 0; ks < 4; ks++) {
                uint2 bh[8], bl[8];
                #pragma unroll
                for (int nf = 0; nf < 8; nf++) {
                    const int kk = nc * 64 + nf * 8 + qr;
                    const int off = frag_off(kk, ks, g);
                    bh[nf] = *reinterpret_cast<const uint2*>(smB0 + off);
                    bl[nf] = *reinterpret_cast<const uint2*>(smB1 + off);
                }
                #pragma unroll
                for (int nf = 0; nf < 8; nf++)   // x0*e0
                    hmma(acc[nf][0], acc[nf][1], acc[nf][2], acc[nf][3],
                         a0r0[ks].x, a0r1[ks].x, a0r0[ks].y, a0r1[ks].y,
                         bh[nf].x, bh[nf].y);
                #pragma unroll
                for (int nf = 0; nf < 8; nf++)   // x0*e1
                    hmma(acc[nf][0], acc[nf][1], acc[nf][2], acc[nf][3],
                         a0r0[ks].x, a0r1[ks].x, a0r0[ks].y, a0r1[ks].y,
                         bl[nf].x, bl[nf].y);
                #pragma unroll
                for (int nf = 0; nf < 8; nf++)   // x1*e0
                    hmma(acc[nf][0], acc[nf][1], acc[nf][2], acc[nf][3],
                         a1r0[ks].x, a1r1[ks].x, a1r0[ks].y, a1r1[ks].y,
                         bh[nf].x, bh[nf].y);
            }
            // scores: rank = esq - 2*dot (xsq constant per row; margin covers it)
            #pragma unroll
            for (int nf = 0; nf < 8; nf++) {
                const int col = nc * 64 + nf * 8 + 2 * g;   // C frag col = 2*(lane%4)
                const float2 eq = *reinterpret_cast<const float2*>(esq + col);
                float s;
                s = __fmaf_rn(-2.0f, acc[nf][0], eq.x); CUPD(0, s, col);
                s = __fmaf_rn(-2.0f, acc[nf][1], eq.y); CUPD(0, s, col + 1);
                s = __fmaf_rn(-2.0f, acc[nf][2], eq.x); CUPD(1, s, col);
                s = __fmaf_rn(-2.0f, acc[nf][3], eq.y); CUPD(1, s, col + 1);
            }
        }
        #undef CUPD

        __syncthreads();   // xsqs ready for rescoring

        // ---- finalize both rows: quad reduce + (fast path | exact rescore) ----
        // All shuffles below are quad-scoped; branch conditions are quad-uniform.
        #pragma unroll
        for (int rr = 0; rr < 2; rr++) {
            const int row = rr ? r1t : r0t;
            float rm = cm[rr];
            rm = fminf(rm, __shfl_xor_sync(qmask, rm, 1));
            rm = fminf(rm, __shfl_xor_sync(qmask, rm, 2));
            const float thr = rm + MARGIN;

            int cnt = 0, first = 0x7FFFFFFF;
            for (int i = 0; i < cn[rr]; i++)
                if (cval[rr][i] <= thr) { if (!cnt) first = cidx[rr][i]; cnt++; }

            int tot = cnt;
            tot += __shfl_xor_sync(qmask, tot, 1);
            tot += __shfl_xor_sync(qmask, tot, 2);
            int ov = cov[rr];
            ov |= __shfl_xor_sync(qmask, ov, 1);
            ov |= __shfl_xor_sync(qmask, ov, 2);

            int winner;
            if (!ov && tot == 1) {
                int wk = (cnt == 1) ? first : 0x7FFFFFFF;
                wk = min(wk, __shfl_xor_sync(qmask, wk, 1));
                wk = min(wk, __shfl_xor_sync(qmask, wk, 2));
                winner = wk;
            } else {
                float bd = CUDART_INF_F; int bk = 0x7FFFFFFF;
                const float xq = xsqs[row];
                if (ov) {                         // pathological: full exact scan
                    for (int k = g; k < VQ_K; k += 4) {
                        const float d = exact_dist(xf, emb, xq, esq[k], k, row);
                        if (d < bd || (d == bd && k < bk)) { bd = d; bk = k; }
                    }
                } else {                          // rescore candidates exactly
                    for (int i = 0; i < cn[rr]; i++) {
                        if (cval[rr][i] > thr) continue;
                        const int k = cidx[rr][i];
                        const float d = exact_dist(xf, emb, xq, esq[k], k, row);
                        if (d < bd || (d == bd && k < bk)) { bd = d; bk = k; }
                    }
                }
                #pragma unroll
                for (int m = 1; m <= 2; m <<= 1) {
                    const float ovv = __shfl_xor_sync(qmask, bd, m);
                    const int   oii = __shfl_xor_sync(qmask, bk, m);
                    if (ovv < bd || (ovv == bd && oii < bk)) { bd = ovv; bk = oii; }
                }
                winner = bk;
            }
            if (g == 0) winners[row] = winner;
        }
        __syncthreads();

        // ---- output: gather winning rows, float4 stores along hw ----
        #pragma unroll
        for (int it = 0; it < 8; it++) {
            const int lin = it * THREADS + tid;
            const int c = lin >> 5, q = lin & 31, p = q * 4;
            float4 v;
            v.x = __ldg(emb + (size_t)winners[p + 0] * VQ_D + c);
            v.y = __ldg(emb + (size_t)winners[p + 1] * VQ_D + c);
            v.z = __ldg(emb + (size_t)winners[p + 2] * VQ_D + c);
            v.w = __ldg(emb + (size_t)winners[p + 3] * VQ_D + c);
            *reinterpret_cast<float4*>(obase + (size_t)c * VQ_HW + p) = v;
        }
        __syncthreads();   // protect smem for next tile's staging
    }
}

extern "C" void kernel_launch(void* const* d_in, const int* in_sizes, int n_in,
                              void* d_out, int out_size) {
    (void)in_sizes; (void)n_in; (void)out_size;
    const float* x   = (const float*)d_in[0];
    const float* emb = (const float*)d_in[1];
    float* out = (float*)d_out;

    cudaFuncSetAttribute(vq_hmma_kernel, cudaFuncAttributeMaxDynamicSharedMemorySize,
                         SMEM_TOTAL);

    vq_hmma_kernel<<<152, THREADS, SMEM_TOTAL>>>(x, emb, out);
}

// round 9
// speedup vs baseline: 7.3485x; 7.3485x over previous
#include <cuda_runtime.h>
#include <cuda_bf16.h>
#include <cstdint>
#include <math_constants.h>

// VectorQuantizer via mma.sync bf16 (3-pass emulated fp32 GEMM) + exact rescore.
// R9: (a) candidate-list compaction (R8's append-only list overflowed for ~75%
// of pixels -> exact full scans dominated at 2.5ms); (b) ldmatrix on a
// chunk-swizzled layout (conflict-free) instead of 4-way-conflicted LDS.64;
// (c) output gather staged through smem for coalescing.

#define VQ_K 512
#define VQ_D 64
#define VQ_HW 4096
#define TILE_M 128
#define NTILES 1024
#define THREADS 256
#define CAP 8
#define MARGIN 1e-4f
#define XFS 132

// ---- shared memory layout (bytes) ----
#define SM_B0  0         // codebook hi bf16 [512 rows][128B]   64 KB
#define SM_B1  65536     // codebook lo bf16                    64 KB
#define SM_A0  131072    // x tile hi bf16 [128 rows][128B]     16 KB
#define SM_A1  147456    // x tile lo bf16                      16 KB
#define SM_XF  163840    // x tile f32 [64][XFS]                33792 B
#define SM_ESQ 197632    // f32 e_sq[512]
#define SM_XSQ 199680    // f32 xsq[128]
#define SM_WIN 200192    // int winners[128]
#define SMEM_TOTAL 200704

// Rows are 128B (64 bf16) = 8 chunks of 16B; chunk stored at position
// chunk ^ (row&7) -> ldmatrix (8 rows x 16B) is bank-conflict-free.
__device__ __forceinline__ int swz(int row, int chunk) {
    return row * 128 + ((chunk ^ (row & 7)) << 4);
}
__device__ __forceinline__ uint32_t sptr(const void* p) {
    return (uint32_t)__cvta_generic_to_shared(p);
}
#define LDSM4(r0, r1, r2, r3, addr)                                            \
    asm volatile("ldmatrix.sync.aligned.m8n8.x4.shared.b16 {%0,%1,%2,%3}, [%4];" \
                 : "=r"(r0), "=r"(r1), "=r"(r2), "=r"(r3) : "r"(addr))

__device__ __forceinline__ void hmma(float& d0, float& d1, float& d2, float& d3,
                                     uint32_t a0, uint32_t a1, uint32_t a2, uint32_t a3,
                                     uint32_t b0, uint32_t b1) {
    asm volatile(
        "mma.sync.aligned.m16n8k16.row.col.f32.bf16.bf16.f32 "
        "{%0,%1,%2,%3}, {%4,%5,%6,%7}, {%8,%9}, {%0,%1,%2,%3};"
        : "+f"(d0), "+f"(d1), "+f"(d2), "+f"(d3)
        : "r"(a0), "r"(a1), "r"(a2), "r"(a3), "r"(b0), "r"(b1));
}

__device__ __forceinline__ uint32_t pack2bf(float a, float b) {
    __nv_bfloat162 h = __floats2bfloat162_rn(a, b);
    return *reinterpret_cast<uint32_t*>(&h);
}
__device__ __forceinline__ float bf_hi(float v) {
    return __bfloat162float(__float2bfloat16(v));
}

// Exact fp32 distance, numerics identical to round-1 (bit-matched reference).
__device__ __forceinline__ float exact_dist(const float* __restrict__ xf,
                                            const float* __restrict__ emb,
                                            float xsq, float esqk, int k, int p) {
    const float4* er = reinterpret_cast<const float4*>(emb + (size_t)k * VQ_D);
    float dot = 0.0f;
    #pragma unroll
    for (int q = 0; q < 16; q++) {
        const float4 f = __ldg(er + q);
        dot = __fmaf_rn(xf[(4 * q + 0) * XFS + p], f.x, dot);
        dot = __fmaf_rn(xf[(4 * q + 1) * XFS + p], f.y, dot);
        dot = __fmaf_rn(xf[(4 * q + 2) * XFS + p], f.z, dot);
        dot = __fmaf_rn(xf[(4 * q + 3) * XFS + p], f.w, dot);
    }
    return __fadd_rn(__fadd_rn(xsq, esqk), __fmul_rn(-2.0f, dot));
}

__global__ __launch_bounds__(THREADS, 1)
void vq_hmma_kernel(const float* __restrict__ x,
                    const float* __restrict__ emb,
                    float* __restrict__ out) {
    extern __shared__ char sm[];
    float* xf      = reinterpret_cast<float*>(sm + SM_XF);
    float* esq     = reinterpret_cast<float*>(sm + SM_ESQ);
    float* xsqs    = reinterpret_cast<float*>(sm + SM_XSQ);
    int*   winners = reinterpret_cast<int*>(sm + SM_WIN);

    const int tid  = threadIdx.x;
    const int wid  = tid >> 5;
    const int lane = tid & 31;
    const int g    = lane & 3;
    const int qr   = lane >> 2;
    const unsigned qmask = 0xFu << (qr * 4);

    // ---- prologue: stage codebook (bf16 hi/lo, swizzled chunks) + exact e_sq ----
    #pragma unroll 4
    for (int it = 0; it < 32; it++) {
        const int lin = it * THREADS + tid;          // 8192 float4s
        const int k = lin >> 4, q = lin & 15;
        const float4 f = __ldg(reinterpret_cast<const float4*>(emb + k * VQ_D) + q);
        const int off = swz(k, q >> 1) + (q & 1) * 8;
        *reinterpret_cast<uint2*>(sm + SM_B0 + off) =
            make_uint2(pack2bf(f.x, f.y), pack2bf(f.z, f.w));
        *reinterpret_cast<uint2*>(sm + SM_B1 + off) =
            make_uint2(pack2bf(f.x - bf_hi(f.x), f.y - bf_hi(f.y)),
                       pack2bf(f.z - bf_hi(f.z), f.w - bf_hi(f.w)));
    }
    for (int k = tid; k < VQ_K; k += THREADS) {
        const float4* er = reinterpret_cast<const float4*>(emb + k * VQ_D);
        float s = 0.0f;
        #pragma unroll
        for (int q = 0; q < 16; q++) {
            const float4 f = __ldg(er + q);
            s = __fadd_rn(s, __fmul_rn(f.x, f.x));
            s = __fadd_rn(s, __fmul_rn(f.y, f.y));
            s = __fadd_rn(s, __fmul_rn(f.z, f.z));
            s = __fadd_rn(s, __fmul_rn(f.w, f.w));
        }
        esq[k] = s;
    }
    __syncthreads();

    for (int tile = blockIdx.x; tile < NTILES; tile += gridDim.x) {
        const int pix0 = tile * TILE_M;
        const int bIdx = pix0 >> 12;
        const int hw0  = pix0 & 4095;
        const float* xbase = x + (size_t)bIdx * VQ_D * VQ_HW + hw0;
        float* obase = out + (size_t)bIdx * VQ_D * VQ_HW + hw0;

        // ---- pass 1: coalesced x load -> xf (f32, channel-major) ----
        #pragma unroll
        for (int it = 0; it < 8; it++) {
            const int lin = it * THREADS + tid;      // 2048 float4s
            const int c = lin >> 5, q = lin & 31, p = q * 4;
            const float4 f = __ldg(reinterpret_cast<const float4*>(
                xbase + (size_t)c * VQ_HW + p));
            *reinterpret_cast<float4*>(xf + c * XFS + p) = f;
        }
        __syncthreads();

        // ---- pass 2: transpose xf -> bf16 hi/lo A tiles (16B chunk stores) ----
        #pragma unroll
        for (int i = 0; i < 4; i++) {
            const int task = i * THREADS + tid;      // 1024 = 128 rows x 8 chunks
            const int p = task & 127, h = task >> 7;
            float v[8];
            #pragma unroll
            for (int j = 0; j < 8; j++) v[j] = xf[(8 * h + j) * XFS + p];
            const int off = swz(p, h);
            *reinterpret_cast<uint4*>(sm + SM_A0 + off) =
                make_uint4(pack2bf(v[0], v[1]), pack2bf(v[2], v[3]),
                           pack2bf(v[4], v[5]), pack2bf(v[6], v[7]));
            *reinterpret_cast<uint4*>(sm + SM_A1 + off) =
                make_uint4(pack2bf(v[0] - bf_hi(v[0]), v[1] - bf_hi(v[1])),
                           pack2bf(v[2] - bf_hi(v[2]), v[3] - bf_hi(v[3])),
                           pack2bf(v[4] - bf_hi(v[4]), v[5] - bf_hi(v[5])),
                           pack2bf(v[6] - bf_hi(v[6]), v[7] - bf_hi(v[7])));
        }
        if (tid < TILE_M) {
            float s = 0.0f;
            #pragma unroll
            for (int c = 0; c < VQ_D; c++) {
                const float v = xf[c * XFS + tid];
                s = __fadd_rn(s, __fmul_rn(v, v));
            }
            xsqs[tid] = s;
        }
        __syncthreads();

        // ---- A fragments via ldmatrix.x4 (conflict-free) ----
        const int arow = wid * 16 + (lane & 7) + ((lane >> 3) & 1) * 8;
        uint32_t aHi[4][4], aLo[4][4];
        #pragma unroll
        for (int ks = 0; ks < 4; ks++) {
            const int ach = 2 * ks + (lane >> 4);
            LDSM4(aHi[ks][0], aHi[ks][1], aHi[ks][2], aHi[ks][3],
                  sptr(sm + SM_A0 + swz(arow, ach)));
            LDSM4(aLo[ks][0], aLo[ks][1], aLo[ks][2], aLo[ks][3],
                  sptr(sm + SM_A1 + swz(arow, ach)));
        }

        // candidate state per row (r0, r1)
        float cm[2]   = {CUDART_INF_F, CUDART_INF_F};
        float cthr[2] = {CUDART_INF_F, CUDART_INF_F};
        int   cn[2] = {0, 0};
        int   cov[2] = {0, 0};
        int   cidx[2][CAP];
        float cval[2][CAP];

        #define CUPD(rr, s, kk)                                                 \
            if ((s) <= cthr[rr]) {                                              \
                if ((s) < cm[rr]) { cm[rr] = (s); cthr[rr] = (s) + MARGIN; }    \
                if (cn[rr] == CAP) {       /* compact: drop stale entries */    \
                    int w = 0;                                                  \
                    for (int z = 0; z < CAP; z++)                               \
                        if (cval[rr][z] <= cthr[rr]) {                          \
                            cval[rr][w] = cval[rr][z];                          \
                            cidx[rr][w] = cidx[rr][z]; w++;                     \
                        }                                                       \
                    cn[rr] = w;                                                 \
                }                                                               \
                if (cn[rr] < CAP) { cidx[rr][cn[rr]] = (kk);                    \
                                    cval[rr][cn[rr]] = (s); cn[rr]++; }         \
                else cov[rr] = 1;                                               \
            }

        const int browo = (lane & 7) + (lane >> 4) * 8;   // row within 16-row pair
        const int bchs  = (lane >> 3) & 1;                // chunk select

        for (int nc = 0; nc < 8; nc++) {          // 8 chunks of 64 codes
            float acc[8][4];
            #pragma unroll
            for (int nf = 0; nf < 8; nf++) {
                acc[nf][0] = 0.f; acc[nf][1] = 0.f; acc[nf][2] = 0.f; acc[nf][3] = 0.f;
            }
            #pragma unroll
            for (int ks = 0; ks < 4; ks++) {
                uint32_t bh[8][2], bl[8][2];
                #pragma unroll
                for (int pr = 0; pr < 4; pr++) {
                    const int row = nc * 64 + pr * 16 + browo;
                    const int ch  = 2 * ks + bchs;
                    LDSM4(bh[2 * pr][0], bh[2 * pr][1], bh[2 * pr + 1][0], bh[2 * pr + 1][1],
                          sptr(sm + SM_B0 + swz(row, ch)));
                    LDSM4(bl[2 * pr][0], bl[2 * pr][1], bl[2 * pr + 1][0], bl[2 * pr + 1][1],
                          sptr(sm + SM_B1 + swz(row, ch)));
                }
                #pragma unroll
                for (int nf = 0; nf < 8; nf++)   // x0*e0
                    hmma(acc[nf][0], acc[nf][1], acc[nf][2], acc[nf][3],
                         aHi[ks][0], aHi[ks][1], aHi[ks][2], aHi[ks][3],
                         bh[nf][0], bh[nf][1]);
                #pragma unroll
                for (int nf = 0; nf < 8; nf++)   // x0*e1
                    hmma(acc[nf][0], acc[nf][1], acc[nf][2], acc[nf][3],
                         aHi[ks][0], aHi[ks][1], aHi[ks][2], aHi[ks][3],
                         bl[nf][0], bl[nf][1]);
                #pragma unroll
                for (int nf = 0; nf < 8; nf++)   // x1*e0
                    hmma(acc[nf][0], acc[nf][1], acc[nf][2], acc[nf][3],
                         aLo[ks][0], aLo[ks][1], aLo[ks][2], aLo[ks][3],
                         bh[nf][0], bh[nf][1]);
            }
            // scores: rank = esq - 2*dot (xsq constant per row; margin covers it)
            #pragma unroll
            for (int nf = 0; nf < 8; nf++) {
                const int col = nc * 64 + nf * 8 + 2 * g;
                const float2 eq = *reinterpret_cast<const float2*>(esq + col);
                float s;
                s = __fmaf_rn(-2.0f, acc[nf][0], eq.x); CUPD(0, s, col);
                s = __fmaf_rn(-2.0f, acc[nf][1], eq.y); CUPD(0, s, col + 1);
                s = __fmaf_rn(-2.0f, acc[nf][2], eq.x); CUPD(1, s, col);
                s = __fmaf_rn(-2.0f, acc[nf][3], eq.y); CUPD(1, s, col + 1);
            }
        }
        #undef CUPD

        __syncthreads();   // xsqs ready for rescoring

        // ---- finalize both rows (quad-scoped shuffles; quad-uniform branches) ----
        #pragma unroll
        for (int rr = 0; rr < 2; rr++) {
            const int row = (rr ? wid * 16 + qr + 8 : wid * 16 + qr);
            float rm = cm[rr];
            rm = fminf(rm, __shfl_xor_sync(qmask, rm, 1));
            rm = fminf(rm, __shfl_xor_sync(qmask, rm, 2));
            const float thr = rm + MARGIN;

            int cnt = 0, first = 0x7FFFFFFF;
            for (int i = 0; i < cn[rr]; i++)
                if (cval[rr][i] <= thr) { if (!cnt) first = cidx[rr][i]; cnt++; }

            int tot = cnt;
            tot += __shfl_xor_sync(qmask, tot, 1);
            tot += __shfl_xor_sync(qmask, tot, 2);
            int ov = cov[rr];
            ov |= __shfl_xor_sync(qmask, ov, 1);
            ov |= __shfl_xor_sync(qmask, ov, 2);

            int winner;
            if (!ov && tot == 1) {
                int wk = (cnt == 1) ? first : 0x7FFFFFFF;
                wk = min(wk, __shfl_xor_sync(qmask, wk, 1));
                wk = min(wk, __shfl_xor_sync(qmask, wk, 2));
                winner = wk;
            } else {
                float bd = CUDART_INF_F; int bk = 0x7FFFFFFF;
                const float xq = xsqs[row];
                if (ov) {                         // pathological: full exact scan
                    for (int k = g; k < VQ_K; k += 4) {
                        const float d = exact_dist(xf, emb, xq, esq[k], k, row);
                        if (d < bd || (d == bd && k < bk)) { bd = d; bk = k; }
                    }
                } else {                          // rescore candidates exactly
                    for (int i = 0; i < cn[rr]; i++) {
                        if (cval[rr][i] > thr) continue;
                        const int k = cidx[rr][i];
                        const float d = exact_dist(xf, emb, xq, esq[k], k, row);
                        if (d < bd || (d == bd && k < bk)) { bd = d; bk = k; }
                    }
                }
                #pragma unroll
                for (int m = 1; m <= 2; m <<= 1) {
                    const float ovv = __shfl_xor_sync(qmask, bd, m);
                    const int   oii = __shfl_xor_sync(qmask, bk, m);
                    if (ovv < bd || (ovv == bd && oii < bk)) { bd = ovv; bk = oii; }
                }
                winner = bk;
            }
            if (g == 0) winners[row] = winner;
        }
        __syncthreads();

        // ---- gather winner rows (coalesced) into xf, then coalesced stores ----
        #pragma unroll
        for (int it = 0; it < 8; it++) {
            const int lin = it * THREADS + tid;   // 2048: 128 pixels x 16 quads
            const int p = lin >> 4, q = lin & 15;
            const float4 f = __ldg(reinterpret_cast<const float4*>(
                emb + (size_t)winners[p] * VQ_D) + q);
            const int c = q * 4;
            xf[(c + 0) * XFS + p] = f.x;
            xf[(c + 1) * XFS + p] = f.y;
            xf[(c + 2) * XFS + p] = f.z;
            xf[(c + 3) * XFS + p] = f.w;
        }
        __syncthreads();
        #pragma unroll
        for (int it = 0; it < 8; it++) {
            const int lin = it * THREADS + tid;
            const int c = lin >> 5, q = lin & 31, p = q * 4;
            const float4 v = *reinterpret_cast<const float4*>(xf + c * XFS + p);
            *reinterpret_cast<float4*>(obase + (size_t)c * VQ_HW + p) = v;
        }
        __syncthreads();   // protect smem for next tile's staging
    }
}

extern "C" void kernel_launch(void* const* d_in, const int* in_sizes, int n_in,
                              void* d_out, int out_size) {
    (void)in_sizes; (void)n_in; (void)out_size;
    const float* x   = (const float*)d_in[0];
    const float* emb = (const float*)d_in[1];
    float* out = (float*)d_out;

    cudaFuncSetAttribute(vq_hmma_kernel, cudaFuncAttributeMaxDynamicSharedMemorySize,
                         SMEM_TOTAL);

    vq_hmma_kernel<<<152, THREADS, SMEM_TOTAL>>>(x, emb, out);
}

// round 10
// speedup vs baseline: 13.9970x; 1.9047x over previous
#include <cuda_runtime.h>
#include <cuda_bf16.h>
#include <cstdint>
#include <math_constants.h>

// VectorQuantizer via mma.sync bf16 (3-pass emulated fp32 GEMM) + exact rescue.
// R10: branchless top-2 (m1,m2,idx) tracking replaces branchy candidate lists;
// 512 threads (16 warps, codebook split N-wise across warp halves) for latency
// hiding; ambiguous rows (gap<=MARGIN) resolved by whole-warp exact fp32 scans
// (numerics bit-matched the reference in R1/R2).

#define VQ_K 512
#define VQ_D 64
#define VQ_HW 4096
#define TILE_M 128
#define NTILES 1024
#define THREADS 512
#define MARGIN 6e-5f
#define XFS 132

// ---- shared memory layout (bytes) ----
#define SM_B0   0        // codebook hi bf16 [512 rows][128B]   64 KB
#define SM_B1   65536    // codebook lo bf16                    64 KB
#define SM_A0   131072   // x tile hi bf16 [128 rows][128B]     16 KB
#define SM_A1   147456   // x tile lo bf16                      16 KB
#define SM_XF   163840   // x tile f32 [64][XFS]                33792 B
#define SM_ESQ  197632   // f32 e_sq[512]
#define SM_XSQ  199680   // f32 xsq[128]
#define SM_WIN  200192   // int winners[128]
#define SM_HM1  200704   // f32 half-min1 [2][128]
#define SM_HM2  201728   // f32 half-min2 [2][128]
#define SM_HIX  202752   // int half-idx  [2][128]
#define SM_AMB  203776   // int ambiguous rows [128]
#define SM_CNT  204288   // int ambiguous count
#define SMEM_TOTAL 204320

// Rows are 128B (64 bf16) = 8 chunks of 16B; chunk at position chunk^(row&7)
// -> ldmatrix over 8 consecutive rows is bank-conflict-free.
__device__ __forceinline__ int swz(int row, int chunk) {
    return row * 128 + ((chunk ^ (row & 7)) << 4);
}
__device__ __forceinline__ uint32_t sptr(const void* p) {
    return (uint32_t)__cvta_generic_to_shared(p);
}
#define LDSM4(r0, r1, r2, r3, addr)                                            \
    asm volatile("ldmatrix.sync.aligned.m8n8.x4.shared.b16 {%0,%1,%2,%3}, [%4];" \
                 : "=r"(r0), "=r"(r1), "=r"(r2), "=r"(r3) : "r"(addr))

__device__ __forceinline__ void hmma(float& d0, float& d1, float& d2, float& d3,
                                     uint32_t a0, uint32_t a1, uint32_t a2, uint32_t a3,
                                     uint32_t b0, uint32_t b1) {
    asm volatile(
        "mma.sync.aligned.m16n8k16.row.col.f32.bf16.bf16.f32 "
        "{%0,%1,%2,%3}, {%4,%5,%6,%7}, {%8,%9}, {%0,%1,%2,%3};"
        : "+f"(d0), "+f"(d1), "+f"(d2), "+f"(d3)
        : "r"(a0), "r"(a1), "r"(a2), "r"(a3), "r"(b0), "r"(b1));
}

__device__ __forceinline__ uint32_t pack2bf(float a, float b) {
    __nv_bfloat162 h = __floats2bfloat162_rn(a, b);
    return *reinterpret_cast<uint32_t*>(&h);
}
__device__ __forceinline__ float bf_hi(float v) {
    return __bfloat162float(__float2bfloat16(v));
}

// Exact fp32 distance, numerics identical to round-1 (bit-matched reference):
// sequential FMA dot, dist = fl(fl(xsq+esq) + (-2*dot)).
__device__ __forceinline__ float exact_dist(const float* __restrict__ xf,
                                            const float* __restrict__ emb,
                                            float xsq, float esqk, int k, int p) {
    const float4* er = reinterpret_cast<const float4*>(emb + (size_t)k * VQ_D);
    float dot = 0.0f;
    #pragma unroll
    for (int q = 0; q < 16; q++) {
        const float4 f = __ldg(er + q);
        dot = __fmaf_rn(xf[(4 * q + 0) * XFS + p], f.x, dot);
        dot = __fmaf_rn(xf[(4 * q + 1) * XFS + p], f.y, dot);
        dot = __fmaf_rn(xf[(4 * q + 2) * XFS + p], f.z, dot);
        dot = __fmaf_rn(xf[(4 * q + 3) * XFS + p], f.w, dot);
    }
    return __fadd_rn(__fadd_rn(xsq, esqk), __fmul_rn(-2.0f, dot));
}

__global__ __launch_bounds__(THREADS, 1)
void vq_hmma_kernel(const float* __restrict__ x,
                    const float* __restrict__ emb,
                    float* __restrict__ out) {
    extern __shared__ char sm[];
    float* xf      = reinterpret_cast<float*>(sm + SM_XF);
    float* esq     = reinterpret_cast<float*>(sm + SM_ESQ);
    float* xsqs    = reinterpret_cast<float*>(sm + SM_XSQ);
    int*   winners = reinterpret_cast<int*>(sm + SM_WIN);
    float* hm1     = reinterpret_cast<float*>(sm + SM_HM1);
    float* hm2     = reinterpret_cast<float*>(sm + SM_HM2);
    int*   hix     = reinterpret_cast<int*>(sm + SM_HIX);
    int*   amb     = reinterpret_cast<int*>(sm + SM_AMB);
    int*   ambcnt  = reinterpret_cast<int*>(sm + SM_CNT);

    const int tid  = threadIdx.x;
    const int wid  = tid >> 5;
    const int lane = tid & 31;
    const int g    = lane & 3;
    const int qr   = lane >> 2;
    const int hid  = wid >> 3;       // code half: 0 -> k<256, 1 -> k>=256
    const int wrow = wid & 7;        // row block

    // ---- prologue: stage codebook (bf16 hi/lo, swizzled chunks) + exact e_sq ----
    #pragma unroll 4
    for (int it = 0; it < 16; it++) {
        const int lin = it * THREADS + tid;          // 8192 float4s
        const int k = lin >> 4, q = lin & 15;
        const float4 f = __ldg(reinterpret_cast<const float4*>(emb + k * VQ_D) + q);
        const int off = swz(k, q >> 1) + (q & 1) * 8;
        *reinterpret_cast<uint2*>(sm + SM_B0 + off) =
            make_uint2(pack2bf(f.x, f.y), pack2bf(f.z, f.w));
        *reinterpret_cast<uint2*>(sm + SM_B1 + off) =
            make_uint2(pack2bf(f.x - bf_hi(f.x), f.y - bf_hi(f.y)),
                       pack2bf(f.z - bf_hi(f.z), f.w - bf_hi(f.w)));
    }
    {
        const int k = tid;
        const float4* er = reinterpret_cast<const float4*>(emb + k * VQ_D);
        float s = 0.0f;
        #pragma unroll
        for (int q = 0; q < 16; q++) {
            const float4 f = __ldg(er + q);
            s = __fadd_rn(s, __fmul_rn(f.x, f.x));
            s = __fadd_rn(s, __fmul_rn(f.y, f.y));
            s = __fadd_rn(s, __fmul_rn(f.z, f.z));
            s = __fadd_rn(s, __fmul_rn(f.w, f.w));
        }
        esq[k] = s;
    }
    __syncthreads();

    for (int tile = blockIdx.x; tile < NTILES; tile += gridDim.x) {
        const int pix0 = tile * TILE_M;
        const int bIdx = pix0 >> 12;
        const int hw0  = pix0 & 4095;
        const float* xbase = x + (size_t)bIdx * VQ_D * VQ_HW + hw0;
        float* obase = out + (size_t)bIdx * VQ_D * VQ_HW + hw0;

        // ---- pass 1: coalesced x load -> xf (f32, channel-major) ----
        #pragma unroll
        for (int it = 0; it < 4; it++) {
            const int lin = it * THREADS + tid;      // 2048 float4s
            const int c = lin >> 5, q = lin & 31, p = q * 4;
            const float4 f = __ldg(reinterpret_cast<const float4*>(
                xbase + (size_t)c * VQ_HW + p));
            *reinterpret_cast<float4*>(xf + c * XFS + p) = f;
        }
        if (tid == 0) *ambcnt = 0;
        __syncthreads();

        // ---- pass 2: transpose xf -> bf16 hi/lo A tiles ----
        #pragma unroll
        for (int i = 0; i < 2; i++) {
            const int task = i * THREADS + tid;      // 1024 = 128 rows x 8 chunks
            const int p = task & 127, h = task >> 7;
            float v[8];
            #pragma unroll
            for (int j = 0; j < 8; j++) v[j] = xf[(8 * h + j) * XFS + p];
            const int off = swz(p, h);
            *reinterpret_cast<uint4*>(sm + SM_A0 + off) =
                make_uint4(pack2bf(v[0], v[1]), pack2bf(v[2], v[3]),
                           pack2bf(v[4], v[5]), pack2bf(v[6], v[7]));
            *reinterpret_cast<uint4*>(sm + SM_A1 + off) =
                make_uint4(pack2bf(v[0] - bf_hi(v[0]), v[1] - bf_hi(v[1])),
                           pack2bf(v[2] - bf_hi(v[2]), v[3] - bf_hi(v[3])),
                           pack2bf(v[4] - bf_hi(v[4]), v[5] - bf_hi(v[5])),
                           pack2bf(v[6] - bf_hi(v[6]), v[7] - bf_hi(v[7])));
        }
        if (tid < TILE_M) {
            float s = 0.0f;
            #pragma unroll
            for (int c = 0; c < VQ_D; c++) {
                const float v = xf[c * XFS + tid];
                s = __fadd_rn(s, __fmul_rn(v, v));
            }
            xsqs[tid] = s;
        }
        __syncthreads();

        // ---- A fragments via ldmatrix.x4 (conflict-free) ----
        const int arow = wrow * 16 + (lane & 7) + ((lane >> 3) & 1) * 8;
        uint32_t aHi[4][4], aLo[4][4];
        #pragma unroll
        for (int ks = 0; ks < 4; ks++) {
            const int ach = 2 * ks + (lane >> 4);
            LDSM4(aHi[ks][0], aHi[ks][1], aHi[ks][2], aHi[ks][3],
                  sptr(sm + SM_A0 + swz(arow, ach)));
            LDSM4(aLo[ks][0], aLo[ks][1], aLo[ks][2], aLo[ks][3],
                  sptr(sm + SM_A1 + swz(arow, ach)));
        }

        // branchless top-2 state per row (r0, r1)
        float m1[2] = {CUDART_INF_F, CUDART_INF_F};
        float m2[2] = {CUDART_INF_F, CUDART_INF_F};
        int   ki[2] = {0x7FFFFFFF, 0x7FFFFFFF};

        #define UPD(rr, s, kk) {                                   \
            const bool lt = (s) < m1[rr];                          \
            m2[rr] = fminf(m2[rr], lt ? m1[rr] : (s));             \
            ki[rr] = lt ? (kk) : ki[rr];                           \
            m1[rr] = lt ? (s) : m1[rr]; }

        const int browo = (lane & 7) + (lane >> 4) * 8;
        const int bchs  = (lane >> 3) & 1;

        for (int nc = 0; nc < 4; nc++) {      // 4 chunks of 64 codes (this half)
            float acc[8][4];
            #pragma unroll
            for (int nf = 0; nf < 8; nf++) {
                acc[nf][0] = 0.f; acc[nf][1] = 0.f; acc[nf][2] = 0.f; acc[nf][3] = 0.f;
            }
            #pragma unroll
            for (int ks = 0; ks < 4; ks++) {
                uint32_t bh[8][2], bl[8][2];
                #pragma unroll
                for (int pr = 0; pr < 4; pr++) {
                    const int row = hid * 256 + nc * 64 + pr * 16 + browo;
                    const int ch  = 2 * ks + bchs;
                    LDSM4(bh[2 * pr][0], bh[2 * pr][1], bh[2 * pr + 1][0], bh[2 * pr + 1][1],
                          sptr(sm + SM_B0 + swz(row, ch)));
                    LDSM4(bl[2 * pr][0], bl[2 * pr][1], bl[2 * pr + 1][0], bl[2 * pr + 1][1],
                          sptr(sm + SM_B1 + swz(row, ch)));
                }
                #pragma unroll
                for (int nf = 0; nf < 8; nf++)   // x0*e0
                    hmma(acc[nf][0], acc[nf][1], acc[nf][2], acc[nf][3],
                         aHi[ks][0], aHi[ks][1], aHi[ks][2], aHi[ks][3],
                         bh[nf][0], bh[nf][1]);
                #pragma unroll
                for (int nf = 0; nf < 8; nf++)   // x0*e1
                    hmma(acc[nf][0], acc[nf][1], acc[nf][2], acc[nf][3],
                         aHi[ks][0], aHi[ks][1], aHi[ks][2], aHi[ks][3],
                         bl[nf][0], bl[nf][1]);
                #pragma unroll
                for (int nf = 0; nf < 8; nf++)   // x1*e0
                    hmma(acc[nf][0], acc[nf][1], acc[nf][2], acc[nf][3],
                         aLo[ks][0], aLo[ks][1], aLo[ks][2], aLo[ks][3],
                         bh[nf][0], bh[nf][1]);
            }
            // scores: rank = esq - 2*dot (xsq constant per row)
            #pragma unroll
            for (int nf = 0; nf < 8; nf++) {
                const int col = hid * 256 + nc * 64 + nf * 8 + 2 * g;
                const float2 eq = *reinterpret_cast<const float2*>(esq + col);
                float s;
                s = __fmaf_rn(-2.0f, acc[nf][0], eq.x); UPD(0, s, col);
                s = __fmaf_rn(-2.0f, acc[nf][1], eq.y); UPD(0, s, col + 1);
                s = __fmaf_rn(-2.0f, acc[nf][2], eq.x); UPD(1, s, col);
                s = __fmaf_rn(-2.0f, acc[nf][3], eq.y); UPD(1, s, col + 1);
            }
        }
        #undef UPD

        // ---- quad reduce (fully converged; no divergence hazards) ----
        #pragma unroll
        for (int rr = 0; rr < 2; rr++) {
            #pragma unroll
            for (int d = 1; d <= 2; d <<= 1) {
                const float o1 = __shfl_xor_sync(0xffffffffu, m1[rr], d);
                const float o2 = __shfl_xor_sync(0xffffffffu, m2[rr], d);
                const int   oi = __shfl_xor_sync(0xffffffffu, ki[rr], d);
                const bool take = (o1 < m1[rr]) || (o1 == m1[rr] && oi < ki[rr]);
                m2[rr] = fminf(fminf(m2[rr], o2), take ? m1[rr] : o1);
                ki[rr] = take ? oi : ki[rr];
                m1[rr] = take ? o1 : m1[rr];
            }
            if (g == 0) {
                const int row = wrow * 16 + qr + rr * 8;
                hm1[hid * 128 + row] = m1[rr];
                hm2[hid * 128 + row] = m2[rr];
                hix[hid * 128 + row] = ki[rr];
            }
        }
        __syncthreads();

        // ---- combine halves; fast path or enqueue ambiguous ----
        if (tid < TILE_M) {
            const int row = tid;
            const float a1 = hm1[row],       a2 = hm2[row];
            const float b1 = hm1[128 + row], b2 = hm2[128 + row];
            const int   ai = hix[row],       bi = hix[128 + row];
            const bool take = (b1 < a1) || (b1 == a1 && bi < ai);
            const float M1 = take ? b1 : a1;
            const int   IX = take ? bi : ai;
            const float M2 = fminf(fminf(a2, b2), take ? a1 : b1);
            if (M2 - M1 > MARGIN) {
                winners[row] = IX;
            } else {
                const int pos = atomicAdd(ambcnt, 1);
                amb[pos] = row;
            }
        }
        __syncthreads();

        // ---- cooperative exact rescue: one warp per ambiguous row ----
        {
            const int namb = *ambcnt;
            for (int i = wid; i < namb; i += 16) {
                const int row = amb[i];
                const float xq = xsqs[row];
                float bd = CUDART_INF_F; int bk = 0x7FFFFFFF;
                #pragma unroll 4
                for (int k = lane; k < VQ_K; k += 32) {
                    const float d = exact_dist(xf, emb, xq, esq[k], k, row);
                    if (d < bd || (d == bd && k < bk)) { bd = d; bk = k; }
                }
                #pragma unroll
                for (int off = 16; off; off >>= 1) {
                    const float od = __shfl_xor_sync(0xffffffffu, bd, off);
                    const int   oi = __shfl_xor_sync(0xffffffffu, bk, off);
                    if (od < bd || (od == bd && oi < bk)) { bd = od; bk = oi; }
                }
                if (lane == 0) winners[row] = bk;
            }
        }
        __syncthreads();

        // ---- gather winner rows (coalesced) into xf, then coalesced stores ----
        #pragma unroll
        for (int it = 0; it < 4; it++) {
            const int lin = it * THREADS + tid;   // 2048: 128 pixels x 16 quads
            const int p = lin >> 4, q = lin & 15;
            const float4 f = __ldg(reinterpret_cast<const float4*>(
                emb + (size_t)winners[p] * VQ_D) + q);
            const int c = q * 4;
            xf[(c + 0) * XFS + p] = f.x;
            xf[(c + 1) * XFS + p] = f.y;
            xf[(c + 2) * XFS + p] = f.z;
            xf[(c + 3) * XFS + p] = f.w;
        }
        __syncthreads();
        #pragma unroll
        for (int it = 0; it < 4; it++) {
            const int lin = it * THREADS + tid;
            const int c = lin >> 5, q = lin & 31, p = q * 4;
            const float4 v = *reinterpret_cast<const float4*>(xf + c * XFS + p);
            *reinterpret_cast<float4*>(obase + (size_t)c * VQ_HW + p) = v;
        }
        __syncthreads();   // protect smem for next tile's staging
    }
}

extern "C" void kernel_launch(void* const* d_in, const int* in_sizes, int n_in,
                              void* d_out, int out_size) {
    (void)in_sizes; (void)n_in; (void)out_size;
    const float* x   = (const float*)d_in[0];
    const float* emb = (const float*)d_in[1];
    float* out = (float*)d_out;

    cudaFuncSetAttribute(vq_hmma_kernel, cudaFuncAttributeMaxDynamicSharedMemorySize,
                         SMEM_TOTAL);

    vq_hmma_kernel<<<152, THREADS, SMEM_TOTAL>>>(x, emb, out);
}